// round 12
// baseline (speedup 1.0000x reference)
#include <cuda_runtime.h>
#include <cuda_fp16.h>
#include <cstdint>

// ---------------- problem constants ----------------
#define NN 100000
#define EE 3200000
#define GG 128
#define DIN 128
#define DH  256
#define DOUT 64
#define BN_EPS 1e-3f
#define NB_SCAN ((NN + 1023) / 1024)   // 98

// ---------------- device scratch (static, no allocs) ----------------
// invariant: g_deg_in/g_deg_out are ZERO at entry of every call
__device__ int      g_deg_in [NN];
__device__ int      g_deg_out[NN];
__device__ float    g_norm_src[NN];
__device__ float    g_norm_dst[NN];
__device__ int      g_off[NN + 1];
__device__ int      g_cursor[NN];
__device__ int      g_bsum[NB_SCAN];
__device__ int2     g_csr_sn[EE];                    // (src, norm_src bits)
__device__ uint32_t g_hx [(size_t)NN * DIN / 2];     // fp16(h) input, packed half2
__device__ uint32_t g_ab [(size_t)NN * DH / 2];      // agg output (fp16)
__device__ uint32_t g_b0 [(size_t)NN * DH / 2];      // layer0 out (fp16)
__device__ uint32_t g_b1 [(size_t)NN * DH / 2];      // layer1 out (fp16)
__device__ uint32_t g_b2 [(size_t)NN * DH / 2];      // layer2 out (fp16)
__device__ __half   g_W0h[DH * DIN];                 // [n][k] fp16
__device__ __half   g_Wh [2 * DH * DH];              // [l][n][k] fp16
__device__ float    g_bf [3 * DH];
__device__ float    g_pool[GG * DH];
__device__ int      g_gcount[GG];

// ---------------- helpers ----------------
__device__ __forceinline__ float2 h2f(uint32_t u) {
    __half2 h = *reinterpret_cast<__half2*>(&u);
    return __half22float2(h);
}

// ---------------- preprocessing ----------------

__global__ void k_deg(const int* __restrict__ src, const int* __restrict__ dst) {
    int e = blockIdx.x * 256 + threadIdx.x;
    if (e < EE) {
        atomicAdd(&g_deg_out[src[e]], 1);
        atomicAdd(&g_deg_in [dst[e]], 1);
    }
    if (e < GG * DH) g_pool[e] = 0.f;
    if (e < GG) g_gcount[e] = 0;
}

__global__ void __launch_bounds__(1024) k_scanA() {
    __shared__ int sh[1024];
    const int t = threadIdx.x;
    const int i = blockIdx.x * 1024 + t;
    int v = (i < NN) ? g_deg_in[i] : 0;
    sh[t] = v;
    __syncthreads();
#pragma unroll
    for (int d = 1; d < 1024; d <<= 1) {
        int u = (t >= d) ? sh[t - d] : 0;
        __syncthreads();
        sh[t] += u;
        __syncthreads();
    }
    if (i < NN) {
        g_off[i] = sh[t] - v;
        g_norm_dst[i] = rsqrtf(fmaxf((float)v, 1.f));
        g_norm_src[i] = rsqrtf(fmaxf((float)g_deg_out[i], 1.f));
    }
    if (t == 1023) g_bsum[blockIdx.x] = sh[t];
}

__global__ void __launch_bounds__(1024) k_scanC() {
    __shared__ int sb[128];
    const int t = threadIdx.x;
    if (t < 128) sb[t] = (t < NB_SCAN) ? g_bsum[t] : 0;
    __syncthreads();
#pragma unroll
    for (int d = 1; d < 128; d <<= 1) {
        int u = 0;
        if (t < 128 && t >= d) u = sb[t - d];
        __syncthreads();
        if (t < 128) sb[t] += u;
        __syncthreads();
    }
    const int boff = (blockIdx.x == 0) ? 0 : sb[blockIdx.x - 1];
    const int i = blockIdx.x * 1024 + t;
    if (i < NN) {
        int o = g_off[i] + boff;
        g_off[i] = o;
        g_cursor[i] = o;
        g_deg_in[i] = 0;
        g_deg_out[i] = 0;
    }
    if (i == 0) g_off[NN] = EE;
}

__global__ void k_csr(const int* __restrict__ src, const int* __restrict__ dst) {
    int e = blockIdx.x * 256 + threadIdx.x;
    if (e < EE) {
        int s = src[e];
        int pos = atomicAdd(&g_cursor[dst[e]], 1);
        g_csr_sn[pos] = make_int2(s, __float_as_int(g_norm_src[s]));
    }
}

__global__ void __launch_bounds__(256) k_cvt(const float* __restrict__ h) {
    size_t i = (size_t)blockIdx.x * 256 + threadIdx.x;
    if (i < (size_t)NN * DIN / 2) {
        float2 f = ((const float2*)h)[i];
        __half2 p = __floats2half2_rn(f.x, f.y);
        g_hx[i] = *reinterpret_cast<uint32_t*>(&p);
    }
}

// fold BN scale into weights (fp16, transposed to [n][k]) and biases (fp32)
__global__ void k_fold(const float* __restrict__ W0, const float* __restrict__ b0,
                       const float* __restrict__ W,  const float* __restrict__ b,
                       const float* __restrict__ gamma, const float* __restrict__ beta,
                       const float* __restrict__ mean,  const float* __restrict__ var) {
    int idx = blockIdx.x * 256 + threadIdx.x;
    if (idx < 2 * DH * DH) {
        int l = idx >> 16;
        int r = idx & (DH * DH - 1);
        int n = r / DH;                 // output col
        int k = r % DH;                 // input row
        float a = gamma[(l + 1) * DH + n] * rsqrtf(var[(l + 1) * DH + n] + BN_EPS);
        g_Wh[idx] = __float2half(W[l * DH * DH + k * DH + n] * a);
    }
    if (idx < DH * DIN) {
        int n = idx / DIN;
        int k = idx % DIN;
        float a = gamma[n] * rsqrtf(var[n] + BN_EPS);
        g_W0h[idx] = __float2half(W0[k * DH + n] * a);
    }
    if (idx < 3 * DH) {
        int l = idx >> 8;
        int j = idx & (DH - 1);
        float a = gamma[idx] * rsqrtf(var[idx] + BN_EPS);
        float bl = (l == 0) ? b0[j] : b[(l - 1) * DH + j];
        g_bf[idx] = bl * a + beta[idx] - mean[idx] * a;
    }
}

// ---------------- aggregation: warp-per-node fp16 gather, fp16 output ----------------
template <int D>
__global__ void __launch_bounds__(256) k_aggw(const uint32_t* __restrict__ xin,
                                              uint32_t* __restrict__ aggb) {
    const int w = blockIdx.x * 8 + (threadIdx.x >> 5);
    if (w >= NN) return;
    const int lane = threadIdx.x & 31;
    const int beg = g_off[w], end = g_off[w + 1];
    constexpr int VALS = D / 32;          // 8 (D=256) or 4 (D=128)
    float acc[VALS];
#pragma unroll
    for (int q = 0; q < VALS; q++) acc[q] = 0.f;

    for (int base = beg; base < end; base += 32) {
        const int m = min(32, end - base);
        const int2 esn = g_csr_sn[base + (lane < m ? lane : 0)];
#pragma unroll 4
        for (int j = 0; j < m; j++) {
            const int   sj = __shfl_sync(0xffffffffu, esn.x, j);
            const float nj = __uint_as_float(__shfl_sync(0xffffffffu, (unsigned)esn.y, j));
            if (D == 256) {
                const uint4 u = __ldg(((const uint4*)xin) + (size_t)sj * 32 + lane);
                float2 f0 = h2f(u.x), f1 = h2f(u.y), f2 = h2f(u.z), f3 = h2f(u.w);
                acc[0] = fmaf(f0.x, nj, acc[0]);
                acc[1] = fmaf(f0.y, nj, acc[1]);
                acc[2] = fmaf(f1.x, nj, acc[2]);
                acc[3] = fmaf(f1.y, nj, acc[3]);
                acc[4] = fmaf(f2.x, nj, acc[4]);
                acc[5] = fmaf(f2.y, nj, acc[5]);
                acc[6] = fmaf(f3.x, nj, acc[6]);
                acc[7] = fmaf(f3.y, nj, acc[7]);
            } else {
                const uint2 u = __ldg(((const uint2*)xin) + (size_t)sj * 32 + lane);
                float2 f0 = h2f(u.x), f1 = h2f(u.y);
                acc[0] = fmaf(f0.x, nj, acc[0]);
                acc[1] = fmaf(f0.y, nj, acc[1]);
                acc[2] = fmaf(f1.x, nj, acc[2]);
                acc[3] = fmaf(f1.y, nj, acc[3]);
            }
        }
    }

    if (D == 256) {
        __half2 p0 = __floats2half2_rn(acc[0], acc[1]);
        __half2 p1 = __floats2half2_rn(acc[2], acc[3]);
        __half2 p2 = __floats2half2_rn(acc[4], acc[5]);
        __half2 p3 = __floats2half2_rn(acc[6], acc[7]);
        uint4 o;
        o.x = *reinterpret_cast<uint32_t*>(&p0);
        o.y = *reinterpret_cast<uint32_t*>(&p1);
        o.z = *reinterpret_cast<uint32_t*>(&p2);
        o.w = *reinterpret_cast<uint32_t*>(&p3);
        ((uint4*)aggb)[(size_t)w * 32 + lane] = o;
    } else {
        __half2 p0 = __floats2half2_rn(acc[0], acc[1]);
        __half2 p1 = __floats2half2_rn(acc[2], acc[3]);
        uint2 o;
        o.x = *reinterpret_cast<uint32_t*>(&p0);
        o.y = *reinterpret_cast<uint32_t*>(&p1);
        ((uint2*)aggb)[(size_t)w * 32 + lane] = o;
    }
}

// ---------------- FP16 tensor-core GEMM ----------------
// C[N x 256] (fp16) = A[N x K] (fp16) @ Bw^T, Bw stored [n][k] fp16.
// epilogue: v = relu(acc * norm_dst[row] + biasf[col]); v += res (fp16, optional)
#define ASTR 40   // fp16 elements per smem row (32 data + 8 pad) -> conflict-free frags
__global__ void __launch_bounds__(256) k_gemm_h(const __half* __restrict__ A, int K,
                                                const __half* __restrict__ Bw,
                                                const float* __restrict__ biasf,
                                                const __half* __restrict__ res,
                                                __half* __restrict__ C) {
    __shared__ __half As[128 * ASTR];
    __shared__ __half Bs[128 * ASTR];
    const int tid  = threadIdx.x;
    const int lane = tid & 31;
    const int warp = tid >> 5;
    const int wm = warp & 3;      // 4 warps x 32 rows
    const int wn = warp >> 2;     // 2 warps x 64 cols
    const int gq  = lane >> 2;    // 0..7
    const int tig = lane & 3;     // 0..3
    const int rowBase = blockIdx.y * 128;
    const int colBase = blockIdx.x * 128;

    const int srow = tid >> 2;
    const int sq   = tid & 3;
    int ar0 = rowBase + srow;        if (ar0 > NN - 1) ar0 = NN - 1;
    int ar1 = rowBase + srow + 64;   if (ar1 > NN - 1) ar1 = NN - 1;

    float acc[2][8][4];
#pragma unroll
    for (int mt = 0; mt < 2; mt++)
#pragma unroll
        for (int nt = 0; nt < 8; nt++)
#pragma unroll
            for (int q = 0; q < 4; q++) acc[mt][nt][q] = 0.f;

    for (int k0 = 0; k0 < K; k0 += 32) {
        {
            uint4 v0 = *(const uint4*)(A + (size_t)ar0 * K + k0 + sq * 8);
            uint4 v1 = *(const uint4*)(A + (size_t)ar1 * K + k0 + sq * 8);
            *(uint4*)(&As[srow * ASTR + sq * 8])        = v0;
            *(uint4*)(&As[(srow + 64) * ASTR + sq * 8]) = v1;
        }
        {
            uint4 b0 = *(const uint4*)(Bw + (size_t)(colBase + srow) * K + k0 + sq * 8);
            uint4 b1 = *(const uint4*)(Bw + (size_t)(colBase + srow + 64) * K + k0 + sq * 8);
            *(uint4*)(&Bs[srow * ASTR + sq * 8])        = b0;
            *(uint4*)(&Bs[(srow + 64) * ASTR + sq * 8]) = b1;
        }
        __syncthreads();

#pragma unroll
        for (int kk = 0; kk < 32; kk += 16) {
            uint32_t af[2][4];
#pragma unroll
            for (int mt = 0; mt < 2; mt++) {
                int m = wm * 32 + mt * 16 + gq;
                af[mt][0] = *(const uint32_t*)(&As[m * ASTR + kk + 2 * tig]);
                af[mt][1] = *(const uint32_t*)(&As[(m + 8) * ASTR + kk + 2 * tig]);
                af[mt][2] = *(const uint32_t*)(&As[m * ASTR + kk + 2 * tig + 8]);
                af[mt][3] = *(const uint32_t*)(&As[(m + 8) * ASTR + kk + 2 * tig + 8]);
            }
#pragma unroll
            for (int nt = 0; nt < 8; nt++) {
                int n = wn * 64 + nt * 8 + gq;
                uint32_t b0 = *(const uint32_t*)(&Bs[n * ASTR + kk + 2 * tig]);
                uint32_t b1 = *(const uint32_t*)(&Bs[n * ASTR + kk + 2 * tig + 8]);
#pragma unroll
                for (int mt = 0; mt < 2; mt++) {
                    asm volatile(
                        "mma.sync.aligned.m16n8k16.row.col.f32.f16.f16.f32 "
                        "{%0,%1,%2,%3}, {%4,%5,%6,%7}, {%8,%9}, {%0,%1,%2,%3};\n"
                        : "+f"(acc[mt][nt][0]), "+f"(acc[mt][nt][1]),
                          "+f"(acc[mt][nt][2]), "+f"(acc[mt][nt][3])
                        : "r"(af[mt][0]), "r"(af[mt][1]), "r"(af[mt][2]), "r"(af[mt][3]),
                          "r"(b0), "r"(b1));
                }
            }
        }
        __syncthreads();
    }

#pragma unroll
    for (int mt = 0; mt < 2; mt++) {
#pragma unroll
        for (int half = 0; half < 2; half++) {
            int r = rowBase + wm * 32 + mt * 16 + half * 8 + gq;
            if (r < NN) {
                float nd = g_norm_dst[r];
#pragma unroll
                for (int nt = 0; nt < 8; nt++) {
                    int c = colBase + wn * 64 + nt * 8 + 2 * tig;
                    float v0 = fmaxf(fmaf(acc[mt][nt][half * 2 + 0], nd, biasf[c]),     0.f);
                    float v1 = fmaxf(fmaf(acc[mt][nt][half * 2 + 1], nd, biasf[c + 1]), 0.f);
                    if (res) {
                        __half2 rv = *reinterpret_cast<const __half2*>(res + (size_t)r * DH + c);
                        float2 rf = __half22float2(rv);
                        v0 += rf.x;
                        v1 += rf.y;
                    }
                    __half2 o = __floats2half2_rn(v0, v1);
                    *reinterpret_cast<__half2*>(C + (size_t)r * DH + c) = o;
                }
            }
        }
    }
}

// ---------------- pooling + head ----------------

__global__ void __launch_bounds__(256) k_pool(const __half* __restrict__ h,
                                              const int* __restrict__ gid) {
    const int f = threadIdx.x;
    int n0 = blockIdx.x * 64;
    int n1 = n0 + 64; if (n1 > NN) n1 = NN;
    if (n0 >= NN) return;
    float acc = 0.f;
    int cnt = 0;
    int cur = gid[n0];
    for (int n = n0; n < n1; n++) {
        int g = gid[n];
        if (g != cur) {
            atomicAdd(&g_pool[cur * DH + f], acc);
            if (f == 0) atomicAdd(&g_gcount[cur], cnt);
            acc = 0.f; cnt = 0; cur = g;
        }
        acc += __half2float(h[(size_t)n * DH + f]);
        cnt++;
    }
    atomicAdd(&g_pool[cur * DH + f], acc);
    if (f == 0) atomicAdd(&g_gcount[cur], cnt);
}

__global__ void __launch_bounds__(64) k_head(const float* __restrict__ Wp,
                                             const float* __restrict__ bp,
                                             float* __restrict__ out) {
    const int g = blockIdx.x;
    const int j = threadIdx.x;
    __shared__ float sp[DH];
    float inv = 1.f / fmaxf((float)g_gcount[g], 1.f);
    for (int k = j; k < DH; k += 64) sp[k] = g_pool[g * DH + k] * inv;
    __syncthreads();
    float s = 0.f;
    for (int k = 0; k < DH; k++)
        s = fmaf(sp[k], Wp[k * DOUT + j], s);
    out[g * DOUT + j] = s + bp[j];
}

// ---------------- launch ----------------
extern "C" void kernel_launch(void* const* d_in, const int* in_sizes, int n_in,
                              void* d_out, int out_size) {
    const float* h    = (const float*)d_in[0];
    const float* W0   = (const float*)d_in[1];
    const float* b0   = (const float*)d_in[2];
    const float* W    = (const float*)d_in[3];
    const float* b    = (const float*)d_in[4];
    const float* bng  = (const float*)d_in[5];
    const float* bnb  = (const float*)d_in[6];
    const float* bnm  = (const float*)d_in[7];
    const float* bnv  = (const float*)d_in[8];
    const float* Wp   = (const float*)d_in[9];
    const float* bp   = (const float*)d_in[10];
    const int*   src  = (const int*)d_in[11];
    const int*   dst  = (const int*)d_in[12];
    const int*   gid  = (const int*)d_in[13];
    float* out = (float*)d_out;

    uint32_t *hx, *ab, *b0h, *b1h, *b2h;
    __half *W0h, *Wh;
    float *bf;
    cudaGetSymbolAddress((void**)&hx,  g_hx);
    cudaGetSymbolAddress((void**)&ab,  g_ab);
    cudaGetSymbolAddress((void**)&b0h, g_b0);
    cudaGetSymbolAddress((void**)&b1h, g_b1);
    cudaGetSymbolAddress((void**)&b2h, g_b2);
    cudaGetSymbolAddress((void**)&W0h, g_W0h);
    cudaGetSymbolAddress((void**)&Wh,  g_Wh);
    cudaGetSymbolAddress((void**)&bf,  g_bf);

    const int nb_e = (EE + 255) / 256;

    k_deg  <<<nb_e, 256>>>(src, dst);
    k_scanA<<<NB_SCAN, 1024>>>();
    k_scanC<<<NB_SCAN, 1024>>>();
    k_csr  <<<nb_e, 256>>>(src, dst);
    k_cvt  <<<(NN * DIN / 2 + 255) / 256, 256>>>(h);
    k_fold <<<(2 * DH * DH + 255) / 256, 256>>>(W0, b0, W, b, bng, bnb, bnm, bnv);

    dim3 gemmGrid(DH / 128, (NN + 127) / 128);
    const int aggGrid = (NN + 7) / 8;

    // layer 0: agg over fp16(h) D=128; GEMM K=128; no residual -> b0 (fp16)
    k_aggw<DIN><<<aggGrid, 256>>>(hx, ab);
    k_gemm_h<<<gemmGrid, 256>>>((const __half*)ab, DIN, W0h, bf,
                                nullptr, (__half*)b0h);

    // layer 1: agg over b0; GEMM K=256; residual b0 -> b1
    k_aggw<DH><<<aggGrid, 256>>>(b0h, ab);
    k_gemm_h<<<gemmGrid, 256>>>((const __half*)ab, DH, Wh, bf + DH,
                                (const __half*)b0h, (__half*)b1h);

    // layer 2: agg over b1; residual b1 -> b2
    k_aggw<DH><<<aggGrid, 256>>>(b1h, ab);
    k_gemm_h<<<gemmGrid, 256>>>((const __half*)ab, DH, Wh + DH * DH, bf + 2 * DH,
                                (const __half*)b1h, (__half*)b2h);

    // pooling + head
    k_pool<<<(NN + 63) / 64, 256>>>((const __half*)b2h, gid);
    k_head<<<GG, DOUT>>>(Wp, bp, out);
}

// round 13
// speedup vs baseline: 1.0443x; 1.0443x over previous
#include <cuda_runtime.h>
#include <cuda_fp16.h>
#include <cstdint>

// ---------------- problem constants ----------------
#define NN 100000
#define EE 3200000
#define GG 128
#define DIN 128
#define DH  256
#define DOUT 64
#define BN_EPS 1e-3f
#define NB_SCAN ((NN + 1023) / 1024)   // 98

// ---------------- device scratch (static, no allocs) ----------------
// invariant: g_deg_in/g_deg_out are ZERO at entry of every call
__device__ int      g_deg_in [NN];
__device__ int      g_deg_out[NN];
__device__ float    g_norm_src[NN];
__device__ float    g_norm_dst[NN];
__device__ int      g_off[NN + 1];
__device__ int      g_cursor[NN];
__device__ int      g_bsum[NB_SCAN];
__device__ int2     g_csr_sn[EE];                    // (src, norm_src bits)
__device__ uint32_t g_hx [(size_t)NN * DIN / 2];     // fp16(h) input, packed half2
__device__ uint32_t g_ab [(size_t)NN * DH / 2];      // agg output (fp16)
__device__ uint32_t g_b0 [(size_t)NN * DH / 2];      // layer0 out (fp16)
__device__ uint32_t g_b1 [(size_t)NN * DH / 2];      // layer1 out (fp16)
__device__ uint32_t g_b2 [(size_t)NN * DH / 2];      // layer2 out (fp16)
__device__ __half   g_W0h[DH * DIN];                 // [n][k] fp16
__device__ __half   g_Wh [2 * DH * DH];              // [l][n][k] fp16
__device__ float    g_bf [3 * DH];
__device__ float    g_pool[GG * DH];
__device__ int      g_gcount[GG];

// ---------------- helpers ----------------
__device__ __forceinline__ float2 h2f(uint32_t u) {
    __half2 h = *reinterpret_cast<__half2*>(&u);
    return __half22float2(h);
}
__device__ __forceinline__ void cp16(uint32_t smem_addr, const void* gptr) {
    asm volatile("cp.async.cg.shared.global [%0], [%1], 16;\n"
                 :: "r"(smem_addr), "l"(gptr));
}

// ---------------- preprocessing ----------------

// degrees via atomics, 4 edges/thread; also zero pool accumulators
__global__ void k_deg(const int4* __restrict__ src4, const int4* __restrict__ dst4) {
    int i = blockIdx.x * 256 + threadIdx.x;
    if (i < EE / 4) {
        int4 s = src4[i];
        int4 d = dst4[i];
        atomicAdd(&g_deg_out[s.x], 1);
        atomicAdd(&g_deg_out[s.y], 1);
        atomicAdd(&g_deg_out[s.z], 1);
        atomicAdd(&g_deg_out[s.w], 1);
        atomicAdd(&g_deg_in[d.x], 1);
        atomicAdd(&g_deg_in[d.y], 1);
        atomicAdd(&g_deg_in[d.z], 1);
        atomicAdd(&g_deg_in[d.w], 1);
    }
    if (i < GG * DH) g_pool[i] = 0.f;
    if (i < GG) g_gcount[i] = 0;
}

__global__ void __launch_bounds__(1024) k_scanA() {
    __shared__ int sh[1024];
    const int t = threadIdx.x;
    const int i = blockIdx.x * 1024 + t;
    int v = (i < NN) ? g_deg_in[i] : 0;
    sh[t] = v;
    __syncthreads();
#pragma unroll
    for (int d = 1; d < 1024; d <<= 1) {
        int u = (t >= d) ? sh[t - d] : 0;
        __syncthreads();
        sh[t] += u;
        __syncthreads();
    }
    if (i < NN) {
        g_off[i] = sh[t] - v;
        g_norm_dst[i] = rsqrtf(fmaxf((float)v, 1.f));
        g_norm_src[i] = rsqrtf(fmaxf((float)g_deg_out[i], 1.f));
    }
    if (t == 1023) g_bsum[blockIdx.x] = sh[t];
}

__global__ void __launch_bounds__(1024) k_scanC() {
    __shared__ int sb[128];
    const int t = threadIdx.x;
    if (t < 128) sb[t] = (t < NB_SCAN) ? g_bsum[t] : 0;
    __syncthreads();
#pragma unroll
    for (int d = 1; d < 128; d <<= 1) {
        int u = 0;
        if (t < 128 && t >= d) u = sb[t - d];
        __syncthreads();
        if (t < 128) sb[t] += u;
        __syncthreads();
    }
    const int boff = (blockIdx.x == 0) ? 0 : sb[blockIdx.x - 1];
    const int i = blockIdx.x * 1024 + t;
    if (i < NN) {
        int o = g_off[i] + boff;
        g_off[i] = o;
        g_cursor[i] = o;
        g_deg_in[i] = 0;
        g_deg_out[i] = 0;
    }
    if (i == 0) g_off[NN] = EE;
}

// CSR scatter, 4 edges/thread, norm pre-gathered
__global__ void k_csr(const int4* __restrict__ src4, const int4* __restrict__ dst4) {
    int i = blockIdx.x * 256 + threadIdx.x;
    if (i < EE / 4) {
        int4 s = src4[i];
        int4 d = dst4[i];
        float n0 = g_norm_src[s.x];
        float n1 = g_norm_src[s.y];
        float n2 = g_norm_src[s.z];
        float n3 = g_norm_src[s.w];
        int p0 = atomicAdd(&g_cursor[d.x], 1);
        int p1 = atomicAdd(&g_cursor[d.y], 1);
        int p2 = atomicAdd(&g_cursor[d.z], 1);
        int p3 = atomicAdd(&g_cursor[d.w], 1);
        g_csr_sn[p0] = make_int2(s.x, __float_as_int(n0));
        g_csr_sn[p1] = make_int2(s.y, __float_as_int(n1));
        g_csr_sn[p2] = make_int2(s.z, __float_as_int(n2));
        g_csr_sn[p3] = make_int2(s.w, __float_as_int(n3));
    }
}

__global__ void __launch_bounds__(256) k_cvt(const float* __restrict__ h) {
    size_t i = (size_t)blockIdx.x * 256 + threadIdx.x;
    if (i < (size_t)NN * DIN / 2) {
        float2 f = ((const float2*)h)[i];
        __half2 p = __floats2half2_rn(f.x, f.y);
        g_hx[i] = *reinterpret_cast<uint32_t*>(&p);
    }
}

// fold BN scale into weights (fp16, transposed to [n][k]) and biases (fp32)
__global__ void k_fold(const float* __restrict__ W0, const float* __restrict__ b0,
                       const float* __restrict__ W,  const float* __restrict__ b,
                       const float* __restrict__ gamma, const float* __restrict__ beta,
                       const float* __restrict__ mean,  const float* __restrict__ var) {
    int idx = blockIdx.x * 256 + threadIdx.x;
    if (idx < 2 * DH * DH) {
        int l = idx >> 16;
        int r = idx & (DH * DH - 1);
        int n = r / DH;
        int k = r % DH;
        float a = gamma[(l + 1) * DH + n] * rsqrtf(var[(l + 1) * DH + n] + BN_EPS);
        g_Wh[idx] = __float2half(W[l * DH * DH + k * DH + n] * a);
    }
    if (idx < DH * DIN) {
        int n = idx / DIN;
        int k = idx % DIN;
        float a = gamma[n] * rsqrtf(var[n] + BN_EPS);
        g_W0h[idx] = __float2half(W0[k * DH + n] * a);
    }
    if (idx < 3 * DH) {
        int l = idx >> 8;
        int j = idx & (DH - 1);
        float a = gamma[idx] * rsqrtf(var[idx] + BN_EPS);
        float bl = (l == 0) ? b0[j] : b[(l - 1) * DH + j];
        g_bf[idx] = bl * a + beta[idx] - mean[idx] * a;
    }
}

// ---------------- aggregation: warp-per-node fp16 gather, fp16 output ----------------
template <int D>
__global__ void __launch_bounds__(256) k_aggw(const uint32_t* __restrict__ xin,
                                              uint32_t* __restrict__ aggb) {
    const int w = blockIdx.x * 8 + (threadIdx.x >> 5);
    if (w >= NN) return;
    const int lane = threadIdx.x & 31;
    const int beg = g_off[w], end = g_off[w + 1];
    constexpr int VALS = D / 32;
    float acc[VALS];
#pragma unroll
    for (int q = 0; q < VALS; q++) acc[q] = 0.f;

    for (int base = beg; base < end; base += 32) {
        const int m = min(32, end - base);
        const int2 esn = g_csr_sn[base + (lane < m ? lane : 0)];
#pragma unroll 4
        for (int j = 0; j < m; j++) {
            const int   sj = __shfl_sync(0xffffffffu, esn.x, j);
            const float nj = __uint_as_float(__shfl_sync(0xffffffffu, (unsigned)esn.y, j));
            if (D == 256) {
                const uint4 u = __ldg(((const uint4*)xin) + (size_t)sj * 32 + lane);
                float2 f0 = h2f(u.x), f1 = h2f(u.y), f2 = h2f(u.z), f3 = h2f(u.w);
                acc[0] = fmaf(f0.x, nj, acc[0]);
                acc[1] = fmaf(f0.y, nj, acc[1]);
                acc[2] = fmaf(f1.x, nj, acc[2]);
                acc[3] = fmaf(f1.y, nj, acc[3]);
                acc[4] = fmaf(f2.x, nj, acc[4]);
                acc[5] = fmaf(f2.y, nj, acc[5]);
                acc[6] = fmaf(f3.x, nj, acc[6]);
                acc[7] = fmaf(f3.y, nj, acc[7]);
            } else {
                const uint2 u = __ldg(((const uint2*)xin) + (size_t)sj * 32 + lane);
                float2 f0 = h2f(u.x), f1 = h2f(u.y);
                acc[0] = fmaf(f0.x, nj, acc[0]);
                acc[1] = fmaf(f0.y, nj, acc[1]);
                acc[2] = fmaf(f1.x, nj, acc[2]);
                acc[3] = fmaf(f1.y, nj, acc[3]);
            }
        }
    }

    if (D == 256) {
        __half2 p0 = __floats2half2_rn(acc[0], acc[1]);
        __half2 p1 = __floats2half2_rn(acc[2], acc[3]);
        __half2 p2 = __floats2half2_rn(acc[4], acc[5]);
        __half2 p3 = __floats2half2_rn(acc[6], acc[7]);
        uint4 o;
        o.x = *reinterpret_cast<uint32_t*>(&p0);
        o.y = *reinterpret_cast<uint32_t*>(&p1);
        o.z = *reinterpret_cast<uint32_t*>(&p2);
        o.w = *reinterpret_cast<uint32_t*>(&p3);
        ((uint4*)aggb)[(size_t)w * 32 + lane] = o;
    } else {
        __half2 p0 = __floats2half2_rn(acc[0], acc[1]);
        __half2 p1 = __floats2half2_rn(acc[2], acc[3]);
        uint2 o;
        o.x = *reinterpret_cast<uint32_t*>(&p0);
        o.y = *reinterpret_cast<uint32_t*>(&p1);
        ((uint2*)aggb)[(size_t)w * 32 + lane] = o;
    }
}

// ---------------- FP16 tensor-core GEMM, double-buffered cp.async ----------------
// C[N x 256] (fp16) = A[N x K] (fp16) @ Bw^T, Bw stored [n][k] fp16.
// epilogue: v = relu(acc * norm_dst[row] + biasf[col]); v += res (fp16, optional)
#define ASTR 40   // fp16 elements per smem row (32 data + 8 pad) -> conflict-free frags
__global__ void __launch_bounds__(256) k_gemm_h(const __half* __restrict__ A, int K,
                                                const __half* __restrict__ Bw,
                                                const float* __restrict__ biasf,
                                                const __half* __restrict__ res,
                                                __half* __restrict__ C) {
    __shared__ __half As[2][128 * ASTR];
    __shared__ __half Bs[2][128 * ASTR];
    const int tid  = threadIdx.x;
    const int lane = tid & 31;
    const int warp = tid >> 5;
    const int wm = warp & 3;      // 4 warps x 32 rows
    const int wn = warp >> 2;     // 2 warps x 64 cols
    const int gq  = lane >> 2;    // 0..7
    const int tig = lane & 3;     // 0..3
    const int rowBase = blockIdx.y * 128;
    const int colBase = blockIdx.x * 128;

    const int srow = tid >> 2;
    const int sq   = tid & 3;
    int ar0 = rowBase + srow;        if (ar0 > NN - 1) ar0 = NN - 1;
    int ar1 = rowBase + srow + 64;   if (ar1 > NN - 1) ar1 = NN - 1;
    const int br0 = colBase + srow;
    const int br1 = colBase + srow + 64;

    const uint32_t sA0 = (uint32_t)__cvta_generic_to_shared(&As[0][srow * ASTR + sq * 8]);
    const uint32_t sA1 = (uint32_t)__cvta_generic_to_shared(&As[0][(srow + 64) * ASTR + sq * 8]);
    const uint32_t sB0 = (uint32_t)__cvta_generic_to_shared(&Bs[0][srow * ASTR + sq * 8]);
    const uint32_t sB1 = (uint32_t)__cvta_generic_to_shared(&Bs[0][(srow + 64) * ASTR + sq * 8]);
    const uint32_t stageBytes = 128 * ASTR * 2;

    const int nChunks = K / 32;

    // issue loads for a K-chunk into stage s
    auto issue = [&](int c, int s) {
        const int k0 = c * 32;
        const uint32_t so = s * stageBytes;
        cp16(sA0 + so, A + (size_t)ar0 * K + k0 + sq * 8);
        cp16(sA1 + so, A + (size_t)ar1 * K + k0 + sq * 8);
        cp16(sB0 + so, Bw + (size_t)br0 * K + k0 + sq * 8);
        cp16(sB1 + so, Bw + (size_t)br1 * K + k0 + sq * 8);
        asm volatile("cp.async.commit_group;\n");
    };

    float acc[2][8][4];
#pragma unroll
    for (int mt = 0; mt < 2; mt++)
#pragma unroll
        for (int nt = 0; nt < 8; nt++)
#pragma unroll
            for (int q = 0; q < 4; q++) acc[mt][nt][q] = 0.f;

    issue(0, 0);

    for (int c = 0; c < nChunks; c++) {
        const int s = c & 1;
        if (c + 1 < nChunks) {
            issue(c + 1, (c + 1) & 1);
            asm volatile("cp.async.wait_group 1;\n");
        } else {
            asm volatile("cp.async.wait_group 0;\n");
        }
        __syncthreads();

#pragma unroll
        for (int kk = 0; kk < 32; kk += 16) {
            uint32_t af[2][4];
#pragma unroll
            for (int mt = 0; mt < 2; mt++) {
                int m = wm * 32 + mt * 16 + gq;
                af[mt][0] = *(const uint32_t*)(&As[s][m * ASTR + kk + 2 * tig]);
                af[mt][1] = *(const uint32_t*)(&As[s][(m + 8) * ASTR + kk + 2 * tig]);
                af[mt][2] = *(const uint32_t*)(&As[s][m * ASTR + kk + 2 * tig + 8]);
                af[mt][3] = *(const uint32_t*)(&As[s][(m + 8) * ASTR + kk + 2 * tig + 8]);
            }
#pragma unroll
            for (int nt = 0; nt < 8; nt++) {
                int n = wn * 64 + nt * 8 + gq;
                uint32_t b0 = *(const uint32_t*)(&Bs[s][n * ASTR + kk + 2 * tig]);
                uint32_t b1 = *(const uint32_t*)(&Bs[s][n * ASTR + kk + 2 * tig + 8]);
#pragma unroll
                for (int mt = 0; mt < 2; mt++) {
                    asm volatile(
                        "mma.sync.aligned.m16n8k16.row.col.f32.f16.f16.f32 "
                        "{%0,%1,%2,%3}, {%4,%5,%6,%7}, {%8,%9}, {%0,%1,%2,%3};\n"
                        : "+f"(acc[mt][nt][0]), "+f"(acc[mt][nt][1]),
                          "+f"(acc[mt][nt][2]), "+f"(acc[mt][nt][3])
                        : "r"(af[mt][0]), "r"(af[mt][1]), "r"(af[mt][2]), "r"(af[mt][3]),
                          "r"(b0), "r"(b1));
                }
            }
        }
        __syncthreads();
    }

#pragma unroll
    for (int mt = 0; mt < 2; mt++) {
#pragma unroll
        for (int half = 0; half < 2; half++) {
            int r = rowBase + wm * 32 + mt * 16 + half * 8 + gq;
            if (r < NN) {
                float nd = g_norm_dst[r];
#pragma unroll
                for (int nt = 0; nt < 8; nt++) {
                    int c = colBase + wn * 64 + nt * 8 + 2 * tig;
                    float v0 = fmaxf(fmaf(acc[mt][nt][half * 2 + 0], nd, biasf[c]),     0.f);
                    float v1 = fmaxf(fmaf(acc[mt][nt][half * 2 + 1], nd, biasf[c + 1]), 0.f);
                    if (res) {
                        __half2 rv = *reinterpret_cast<const __half2*>(res + (size_t)r * DH + c);
                        float2 rf = __half22float2(rv);
                        v0 += rf.x;
                        v1 += rf.y;
                    }
                    __half2 o = __floats2half2_rn(v0, v1);
                    *reinterpret_cast<__half2*>(C + (size_t)r * DH + c) = o;
                }
            }
        }
    }
}

// ---------------- pooling + head ----------------

__global__ void __launch_bounds__(256) k_pool(const __half* __restrict__ h,
                                              const int* __restrict__ gid) {
    const int f = threadIdx.x;
    int n0 = blockIdx.x * 64;
    int n1 = n0 + 64; if (n1 > NN) n1 = NN;
    if (n0 >= NN) return;
    float acc = 0.f;
    int cnt = 0;
    int cur = gid[n0];
    for (int n = n0; n < n1; n++) {
        int g = gid[n];
        if (g != cur) {
            atomicAdd(&g_pool[cur * DH + f], acc);
            if (f == 0) atomicAdd(&g_gcount[cur], cnt);
            acc = 0.f; cnt = 0; cur = g;
        }
        acc += __half2float(h[(size_t)n * DH + f]);
        cnt++;
    }
    atomicAdd(&g_pool[cur * DH + f], acc);
    if (f == 0) atomicAdd(&g_gcount[cur], cnt);
}

__global__ void __launch_bounds__(64) k_head(const float* __restrict__ Wp,
                                             const float* __restrict__ bp,
                                             float* __restrict__ out) {
    const int g = blockIdx.x;
    const int j = threadIdx.x;
    __shared__ float sp[DH];
    float inv = 1.f / fmaxf((float)g_gcount[g], 1.f);
    for (int k = j; k < DH; k += 64) sp[k] = g_pool[g * DH + k] * inv;
    __syncthreads();
    float s = 0.f;
    for (int k = 0; k < DH; k++)
        s = fmaf(sp[k], Wp[k * DOUT + j], s);
    out[g * DOUT + j] = s + bp[j];
}

// ---------------- launch ----------------
extern "C" void kernel_launch(void* const* d_in, const int* in_sizes, int n_in,
                              void* d_out, int out_size) {
    const float* h    = (const float*)d_in[0];
    const float* W0   = (const float*)d_in[1];
    const float* b0   = (const float*)d_in[2];
    const float* W    = (const float*)d_in[3];
    const float* b    = (const float*)d_in[4];
    const float* bng  = (const float*)d_in[5];
    const float* bnb  = (const float*)d_in[6];
    const float* bnm  = (const float*)d_in[7];
    const float* bnv  = (const float*)d_in[8];
    const float* Wp   = (const float*)d_in[9];
    const float* bp   = (const float*)d_in[10];
    const int*   src  = (const int*)d_in[11];
    const int*   dst  = (const int*)d_in[12];
    const int*   gid  = (const int*)d_in[13];
    float* out = (float*)d_out;

    uint32_t *hx, *ab, *b0h, *b1h, *b2h;
    __half *W0h, *Wh;
    float *bf;
    cudaGetSymbolAddress((void**)&hx,  g_hx);
    cudaGetSymbolAddress((void**)&ab,  g_ab);
    cudaGetSymbolAddress((void**)&b0h, g_b0);
    cudaGetSymbolAddress((void**)&b1h, g_b1);
    cudaGetSymbolAddress((void**)&b2h, g_b2);
    cudaGetSymbolAddress((void**)&W0h, g_W0h);
    cudaGetSymbolAddress((void**)&Wh,  g_Wh);
    cudaGetSymbolAddress((void**)&bf,  g_bf);

    const int nb_e4 = (EE / 4 + 255) / 256;

    k_deg  <<<nb_e4, 256>>>((const int4*)src, (const int4*)dst);
    k_scanA<<<NB_SCAN, 1024>>>();
    k_scanC<<<NB_SCAN, 1024>>>();
    k_csr  <<<nb_e4, 256>>>((const int4*)src, (const int4*)dst);
    k_cvt  <<<(NN * DIN / 2 + 255) / 256, 256>>>(h);
    k_fold <<<(2 * DH * DH + 255) / 256, 256>>>(W0, b0, W, b, bng, bnb, bnm, bnv);

    dim3 gemmGrid(DH / 128, (NN + 127) / 128);
    const int aggGrid = (NN + 7) / 8;

    // layer 0: agg over fp16(h) D=128; GEMM K=128; no residual -> b0 (fp16)
    k_aggw<DIN><<<aggGrid, 256>>>(hx, ab);
    k_gemm_h<<<gemmGrid, 256>>>((const __half*)ab, DIN, W0h, bf,
                                nullptr, (__half*)b0h);

    // layer 1: agg over b0; GEMM K=256; residual b0 -> b1
    k_aggw<DH><<<aggGrid, 256>>>(b0h, ab);
    k_gemm_h<<<gemmGrid, 256>>>((const __half*)ab, DH, Wh, bf + DH,
                                (const __half*)b0h, (__half*)b1h);

    // layer 2: agg over b1; residual b1 -> b2
    k_aggw<DH><<<aggGrid, 256>>>(b1h, ab);
    k_gemm_h<<<gemmGrid, 256>>>((const __half*)ab, DH, Wh + DH * DH, bf + 2 * DH,
                                (const __half*)b1h, (__half*)b2h);

    // pooling + head
    k_pool<<<(NN + 63) / 64, 256>>>((const __half*)b2h, gid);
    k_head<<<GG, DOUT>>>(Wp, bp, out);
}